// round 5
// baseline (speedup 1.0000x reference)
#include <cuda_runtime.h>

// waspGridSpatialIntegral: input [B=64, 2, W=512, W=512] fp32.
//   out[:,0,:,:] = cumsum(in[:,0,:,:], axis=-1)  (contiguous width)
//   out[:,1,:,:] = cumsum(in[:,1,:,:], axis=-2)  (height, stride W)
//
// Pure HBM streaming: 268 MB traffic. One fused launch:
//   blocks [0, 256)        : column scans, channel 1 (long-running -> lowest bid)
//   blocks [256, 256+32768): row scans, channel 0 (one block per row)
//
// R4: column loop software-pipelined (double buffer of 32). R3's loop
// alternated load phase / drain phase (load duty cycle ~50%); now batch i+1's
// loads issue before batch i's accumulate+store drain, keeping 32-64 lines
// in flight per warp continuously. Last iteration peeled (no predicated loads
// in the steady state).

#define W      512
#define WW     (512 * 512)
#define B      64
#define NROWS  (B * W)              // 32768 channel-0 rows
#define CTILES 4                    // 512 cols / 128 threads
#define NCOLB  (B * CTILES)         // 256 channel-1 blocks
#define UNR    32                   // column batch depth per pipeline stage

__global__ __launch_bounds__(128) void wasp_integral_kernel(
    const float* __restrict__ in, float* __restrict__ out)
{
    const int bid = blockIdx.x;
    const int tid = threadIdx.x;

    if (bid < NCOLB) {
        // ------- channel 1: column scan (cumsum along y, stride W) -------
        const int b    = bid >> 2;
        const int tile = bid & 3;
        const int col  = tile * 128 + tid;
        const float* src = in  + (size_t)(b * 2 + 1) * WW + col;
        float*       dst = out + (size_t)(b * 2 + 1) * WW + col;

        float buf0[UNR], buf1[UNR];

        // prologue: batch 0 -> buf0
        #pragma unroll
        for (int i = 0; i < UNR; ++i)
            buf0[i] = __ldcs(src + (size_t)i * W);

        float acc = 0.0f;
        // steady state: W/UNR = 16 batches; process 14 here (pairs), peel last 2
        #pragma unroll
        for (int r = 0; r < W - 2 * UNR; r += 2 * UNR) {
            #pragma unroll
            for (int i = 0; i < UNR; ++i)               // issue batch r+UNR
                buf1[i] = __ldcs(src + (size_t)(r + UNR + i) * W);
            #pragma unroll
            for (int i = 0; i < UNR; ++i) {             // drain batch r
                acc += buf0[i];
                __stcs(dst + (size_t)(r + i) * W, acc);
            }
            #pragma unroll
            for (int i = 0; i < UNR; ++i)               // issue batch r+2*UNR
                buf0[i] = __ldcs(src + (size_t)(r + 2 * UNR + i) * W);
            #pragma unroll
            for (int i = 0; i < UNR; ++i) {             // drain batch r+UNR
                acc += buf1[i];
                __stcs(dst + (size_t)(r + UNR + i) * W, acc);
            }
        }
        // epilogue: batches W-2*UNR (in buf0) and W-UNR
        {
            const int r = W - 2 * UNR;
            #pragma unroll
            for (int i = 0; i < UNR; ++i)
                buf1[i] = __ldcs(src + (size_t)(r + UNR + i) * W);
            #pragma unroll
            for (int i = 0; i < UNR; ++i) {
                acc += buf0[i];
                __stcs(dst + (size_t)(r + i) * W, acc);
            }
            #pragma unroll
            for (int i = 0; i < UNR; ++i) {
                acc += buf1[i];
                __stcs(dst + (size_t)(r + UNR + i) * W, acc);
            }
        }
    } else {
        // ------- channel 0: row scan (cumsum along x, contiguous) -------
        const int rowid = bid - NCOLB;
        const int b     = rowid >> 9;
        const int y     = rowid & 511;
        const size_t base = (size_t)(b * 2) * WW + (size_t)y * W;

        const float4* src = reinterpret_cast<const float4*>(in + base);
        float4*       dst = reinterpret_cast<float4*>(out + base);

        float4 v = __ldcs(src + tid);
        v.y += v.x; v.z += v.y; v.w += v.z;   // local inclusive scan of 4

        const int lane = tid & 31;
        const int wid  = tid >> 5;

        float t = v.w;                         // warp scan of thread totals
        #pragma unroll
        for (int d = 1; d < 32; d <<= 1) {
            float n = __shfl_up_sync(0xFFFFFFFFu, t, d);
            if (lane >= d) t += n;
        }

        __shared__ float wsum[4];
        if (lane == 31) wsum[wid] = t;
        __syncthreads();

        float off = t - v.w;                   // intra-warp exclusive prefix
        #pragma unroll
        for (int w = 0; w < 3; ++w)
            if (wid > w) off += wsum[w];

        v.x += off; v.y += off; v.z += off; v.w += off;
        __stcs(dst + tid, v);
    }
}

extern "C" void kernel_launch(void* const* d_in, const int* in_sizes, int n_in,
                              void* d_out, int out_size)
{
    const float* in  = (const float*)d_in[0];
    float*       out = (float*)d_out;
    wasp_integral_kernel<<<NCOLB + NROWS, 128>>>(in, out);
}

// round 6
// speedup vs baseline: 1.1236x; 1.1236x over previous
#include <cuda_runtime.h>

// waspGridSpatialIntegral: input [B=64, 2, W=512, W=512] fp32.
//   out[:,0,:,:] = cumsum(in[:,0,:,:], axis=-1)  (contiguous width)
//   out[:,1,:,:] = cumsum(in[:,1,:,:], axis=-2)  (height, stride W)
//
// Pure HBM streaming: 268 MB traffic. One fused launch:
//   blocks [0, 256)        : column scans, channel 1 (long pole -> lowest bid)
//   blocks [256, 256+32768): row scans, channel 0 (one block per row)
//
// R6: column loop uses a 16/16 double buffer. R5's 32/32 double buffer fixed
// the load-duty-cycle bubble but cost 72 regs and tanked the row blocks'
// occupancy (66.7% -> 38.2%). 16/16 keeps total data regs at R3's level
// (~32) while still overlapping each half-batch's loads with the other
// half's accumulate+store drain.

#define W      512
#define WW     (512 * 512)
#define B      64
#define NROWS  (B * W)              // 32768 channel-0 rows
#define CTILES 4                    // 512 cols / 128 threads
#define NCOLB  (B * CTILES)         // 256 channel-1 blocks
#define HB     16                   // half-batch depth (double buffered)

__global__ __launch_bounds__(128) void wasp_integral_kernel(
    const float* __restrict__ in, float* __restrict__ out)
{
    const int bid = blockIdx.x;
    const int tid = threadIdx.x;

    if (bid < NCOLB) {
        // ------- channel 1: column scan (cumsum along y, stride W) -------
        const int b    = bid >> 2;
        const int tile = bid & 3;
        const int col  = tile * 128 + tid;
        const float* src = in  + (size_t)(b * 2 + 1) * WW + col;
        float*       dst = out + (size_t)(b * 2 + 1) * WW + col;

        float bufA[HB], bufB[HB];

        // prologue: half-batch 0 -> bufA
        #pragma unroll
        for (int i = 0; i < HB; ++i)
            bufA[i] = __ldcs(src + (size_t)i * W);

        float acc = 0.0f;
        // W/HB = 32 half-batches; steady state handles pairs, last pair peeled
        #pragma unroll
        for (int r = 0; r < W - 2 * HB; r += 2 * HB) {
            #pragma unroll
            for (int i = 0; i < HB; ++i)                 // issue r+HB
                bufB[i] = __ldcs(src + (size_t)(r + HB + i) * W);
            #pragma unroll
            for (int i = 0; i < HB; ++i) {               // drain r
                acc += bufA[i];
                __stcs(dst + (size_t)(r + i) * W, acc);
            }
            #pragma unroll
            for (int i = 0; i < HB; ++i)                 // issue r+2*HB
                bufA[i] = __ldcs(src + (size_t)(r + 2 * HB + i) * W);
            #pragma unroll
            for (int i = 0; i < HB; ++i) {               // drain r+HB
                acc += bufB[i];
                __stcs(dst + (size_t)(r + HB + i) * W, acc);
            }
        }
        // epilogue: last two half-batches (bufA holds W-2*HB)
        {
            const int r = W - 2 * HB;
            #pragma unroll
            for (int i = 0; i < HB; ++i)
                bufB[i] = __ldcs(src + (size_t)(r + HB + i) * W);
            #pragma unroll
            for (int i = 0; i < HB; ++i) {
                acc += bufA[i];
                __stcs(dst + (size_t)(r + i) * W, acc);
            }
            #pragma unroll
            for (int i = 0; i < HB; ++i) {
                acc += bufB[i];
                __stcs(dst + (size_t)(r + HB + i) * W, acc);
            }
        }
    } else {
        // ------- channel 0: row scan (cumsum along x, contiguous) -------
        const int rowid = bid - NCOLB;
        const int b     = rowid >> 9;
        const int y     = rowid & 511;
        const size_t base = (size_t)(b * 2) * WW + (size_t)y * W;

        const float4* src = reinterpret_cast<const float4*>(in + base);
        float4*       dst = reinterpret_cast<float4*>(out + base);

        float4 v = __ldcs(src + tid);
        v.y += v.x; v.z += v.y; v.w += v.z;   // local inclusive scan of 4

        const int lane = tid & 31;
        const int wid  = tid >> 5;

        float t = v.w;                         // warp scan of thread totals
        #pragma unroll
        for (int d = 1; d < 32; d <<= 1) {
            float n = __shfl_up_sync(0xFFFFFFFFu, t, d);
            if (lane >= d) t += n;
        }

        __shared__ float wsum[4];
        if (lane == 31) wsum[wid] = t;
        __syncthreads();

        float off = t - v.w;                   // intra-warp exclusive prefix
        #pragma unroll
        for (int w = 0; w < 3; ++w)
            if (wid > w) off += wsum[w];

        v.x += off; v.y += off; v.z += off; v.w += off;
        __stcs(dst + tid, v);
    }
}

extern "C" void kernel_launch(void* const* d_in, const int* in_sizes, int n_in,
                              void* d_out, int out_size)
{
    const float* in  = (const float*)d_in[0];
    float*       out = (float*)d_out;
    wasp_integral_kernel<<<NCOLB + NROWS, 128>>>(in, out);
}